// round 9
// baseline (speedup 1.0000x reference)
#include <cuda_runtime.h>
#include <cuda_fp16.h>
#include <cstdint>

// QuantizedLinear on GB300 (sm_103a harness, compute_103 virtual arch -> legacy
// mma.sync.m16n8k16 path; tcgen05 PTX rejected by ptxas at this target).
//   y[b,o] = scale[o] * sum_k x[b,k] * (q[o,k] - 8)
//
// Round 9: eliminate the W prepass entirely. Raw packed W (1 byte per int32,
// 2 nibbles) costs the same DRAM bytes as fp16 W per value, so the GEMM
// producers LDG the raw words and dequantize into smem fp16 in-kernel.
// Prep = x->fp16 only (8 MB). GEMM: 128x128 CTA (4 warps @ 64x64), KC=32,
// 4-stage pipeline, one barrier per chunk, 80B-padded smem rows (no swizzle,
// conflict-free), 2 CTAs/SM, grid 256.

static constexpr int M_DIM = 512;
static constexpr int N_DIM = 8192;
static constexpr int K_DIM = 8192;
static constexpr int KWORDS = K_DIM / 2;           // packed words per W row (4096)

static constexpr int BM = 128;
static constexpr int BN = 128;
static constexpr int KC = 32;                      // k per chunk
static constexpr int STAGES = 4;
static constexpr int NCHUNK = K_DIM / KC;          // 256
static constexpr int NTHREADS = 128;               // 4 warps, 2x2 of 64x64

static constexpr int ROWB = 80;                    // 64B data + 16B pad
static constexpr int A_BYTES = BM * ROWB;          // 10240
static constexpr int B_BYTES = BN * ROWB;          // 10240
static constexpr int STAGE_BYTES = A_BYTES + B_BYTES;      // 20480
static constexpr int SMEM_BYTES  = STAGES * STAGE_BYTES;   // 81920

static constexpr int XCONV_BLOCKS = (M_DIM * K_DIM / 4) / 256;   // 4096

// -------- scratch (device global; no runtime allocation) --------
__device__ __align__(16) __half g_xh[(size_t)M_DIM * K_DIM];     // 8 MB

// ---------------- helpers ----------------
__device__ __forceinline__ uint32_t smem_u32(const void* p) {
    uint32_t a;
    asm("{ .reg .u64 t; cvta.to.shared.u64 t, %1; cvt.u32.u64 %0, t; }"
        : "=r"(a) : "l"(p));
    return a;
}

// (1024+q) - 1032 = q - 8, exact in fp16, both lanes
__device__ __forceinline__ uint32_t dq_sub(uint32_t v) {
    uint32_t r;
    asm("sub.rn.f16x2 %0, %1, %2;" : "=r"(r) : "r"(v), "r"(0x64086408u));
    return r;
}

// packed word (byte) -> fp16x2 {k even = hi nibble, k odd = lo nibble}, q-8 exact
__device__ __forceinline__ uint32_t dqw(uint32_t w) {
    uint32_t t = ((w >> 4) & 0xFu) | 0x64006400u;
    t |= (w << 16) & 0x000F0000u;
    return dq_sub(t);
}

__device__ __forceinline__ void cp_async16(uint32_t dst, const void* src) {
    asm volatile("cp.async.cg.shared.global [%0], [%1], 16;"
                 :: "r"(dst), "l"(src) : "memory");
}
__device__ __forceinline__ void cp_commit() {
    asm volatile("cp.async.commit_group;" ::: "memory");
}
template <int N>
__device__ __forceinline__ void cp_wait() {
    asm volatile("cp.async.wait_group %0;" :: "n"(N) : "memory");
}

__device__ __forceinline__ void ldmatrix4(uint32_t& r0, uint32_t& r1,
                                          uint32_t& r2, uint32_t& r3,
                                          uint32_t addr) {
    asm volatile("ldmatrix.sync.aligned.m8n8.x4.shared.b16 {%0,%1,%2,%3}, [%4];"
                 : "=r"(r0), "=r"(r1), "=r"(r2), "=r"(r3) : "r"(addr));
}

__device__ __forceinline__ void hmma(float* d,
                                     uint32_t a0, uint32_t a1, uint32_t a2, uint32_t a3,
                                     uint32_t b0, uint32_t b1) {
    asm volatile(
        "mma.sync.aligned.m16n8k16.row.col.f32.f16.f16.f32 "
        "{%0,%1,%2,%3}, {%4,%5,%6,%7}, {%8,%9}, {%0,%1,%2,%3};"
        : "+f"(d[0]), "+f"(d[1]), "+f"(d[2]), "+f"(d[3])
        : "r"(a0), "r"(a1), "r"(a2), "r"(a3), "r"(b0), "r"(b1));
}

// ---------------- prepass: x f32 -> fp16 ----------------
__global__ void prep_kernel(const float* __restrict__ x) {
    int i = blockIdx.x * blockDim.x + threadIdx.x;      // float4 index
    float4 v = reinterpret_cast<const float4*>(x)[i];
    reinterpret_cast<__half2*>(g_xh)[2 * i + 0] = __floats2half2_rn(v.x, v.y);
    reinterpret_cast<__half2*>(g_xh)[2 * i + 1] = __floats2half2_rn(v.z, v.w);
}

// ---------------- HMMA GEMM with in-kernel W dequant ----------------
__global__ __launch_bounds__(NTHREADS, 2)
void qgemm_kernel(const int* __restrict__ packed,
                  const float* __restrict__ scale, float* __restrict__ y) {
    extern __shared__ __align__(128) char sb[];
    const uint32_t sb32 = smem_u32(sb);

    const int tid = threadIdx.x;
    const int wid = tid >> 5;
    const int lid = tid & 31;
    const int N0 = blockIdx.x * BN;
    const int M0 = blockIdx.y * BM;

    const int wm = wid >> 1;            // 0..1 : m offset wm*64
    const int wn = wid & 1;             // 0..1 : n offset wn*64

    const __half* xb = g_xh + (size_t)M0 * K_DIM;
    // B: thread t owns W row N0+t; per chunk 16 packed words (64B) contiguous
    const unsigned* wrow =
        reinterpret_cast<const unsigned*>(packed) + (size_t)(N0 + tid) * KWORDS;

    float acc[4][8][4];
    #pragma unroll
    for (int i = 0; i < 4; i++)
        #pragma unroll
        for (int j = 0; j < 8; j++)
            #pragma unroll
            for (int v = 0; v < 4; v++)
                acc[i][j][v] = 0.0f;

    // ---- prologue: stages 0..S-2 <- chunks 0..S-2 ----
    #pragma unroll
    for (int s = 0; s < STAGES - 1; s++) {
        const int k0 = s * KC;
        const uint32_t As = sb32 + s * STAGE_BYTES;
        const uint32_t Bs = As + A_BYTES;
        #pragma unroll
        for (int i = 0; i < 4; i++) {                  // A: 512 segs (128r x 4)
            int seg = tid + i * NTHREADS;
            int m = seg >> 2, j = seg & 3;
            cp_async16(As + (uint32_t)(m * ROWB + j * 16),
                       xb + (size_t)m * K_DIM + k0 + j * 8);
        }
        cp_commit();
        // B: LDG 16 words, dequant, STS (one-time latency, prologue only)
        const uint4* src = reinterpret_cast<const uint4*>(wrow + (k0 >> 1));
        uint4 p0 = src[0], p1 = src[1], p2 = src[2], p3 = src[3];
        uint4 q;
        q.x = dqw(p0.x); q.y = dqw(p0.y); q.z = dqw(p0.z); q.w = dqw(p0.w);
        *reinterpret_cast<uint4*>(sb + (Bs - sb32) + tid * ROWB + 0)  = q;
        q.x = dqw(p1.x); q.y = dqw(p1.y); q.z = dqw(p1.z); q.w = dqw(p1.w);
        *reinterpret_cast<uint4*>(sb + (Bs - sb32) + tid * ROWB + 16) = q;
        q.x = dqw(p2.x); q.y = dqw(p2.y); q.z = dqw(p2.z); q.w = dqw(p2.w);
        *reinterpret_cast<uint4*>(sb + (Bs - sb32) + tid * ROWB + 32) = q;
        q.x = dqw(p3.x); q.y = dqw(p3.y); q.z = dqw(p3.z); q.w = dqw(p3.w);
        *reinterpret_cast<uint4*>(sb + (Bs - sb32) + tid * ROWB + 48) = q;
    }

    const uint32_t a_warp = (uint32_t)(wm * 64 * ROWB);
    const uint32_t b_warp = (uint32_t)(wn * 64 * ROWB);
    const int ql = lid >> 3;            // 0..3
    const int qr = lid & 7;

    for (int c = 0; c < NCHUNK; c++) {
        cp_wait<STAGES - 2>();
        __syncthreads();

        // ---- issue loads for chunk c+S-1 into stage (c-1)%S (freed at c-1) ----
        const int fc = c + STAGES - 1;
        const bool fetch = (fc < NCHUNK);
        uint4 p0, p1, p2, p3;
        uint32_t fB = 0;
        if (fetch) {
            const int fst = fc & (STAGES - 1);
            const int k0 = fc * KC;
            const uint32_t As = sb32 + fst * STAGE_BYTES;
            fB = fst * STAGE_BYTES + A_BYTES;
            // B LDG first (longest latency)
            const uint4* src = reinterpret_cast<const uint4*>(wrow + (k0 >> 1));
            p0 = src[0]; p1 = src[1]; p2 = src[2]; p3 = src[3];
            #pragma unroll
            for (int i = 0; i < 4; i++) {
                int seg = tid + i * NTHREADS;
                int m = seg >> 2, j = seg & 3;
                cp_async16(As + (uint32_t)(m * ROWB + j * 16),
                           xb + (size_t)m * K_DIM + k0 + j * 8);
            }
        }
        cp_commit();

        // ---- compute chunk c ----
        {
            const int st = c & (STAGES - 1);
            const uint32_t As = sb32 + st * STAGE_BYTES + a_warp;
            const uint32_t Bs = sb32 + st * STAGE_BYTES + A_BYTES + b_warp;

            #pragma unroll
            for (int kk = 0; kk < 2; kk++) {
                uint32_t a[4][4];
                #pragma unroll
                for (int i = 0; i < 4; i++) {
                    uint32_t addr = As + (uint32_t)(
                        (i * 16 + (lid & 15)) * ROWB + kk * 32 + (lid >> 4) * 16);
                    ldmatrix4(a[i][0], a[i][1], a[i][2], a[i][3], addr);
                }
                uint32_t b[8][2];
                #pragma unroll
                for (int g = 0; g < 4; g++) {
                    int row = g * 16 + (ql >> 1) * 8 + qr;
                    int kh  = ql & 1;
                    uint32_t addr = Bs + (uint32_t)(
                        row * ROWB + kk * 32 + kh * 16);
                    ldmatrix4(b[2*g][0], b[2*g][1], b[2*g+1][0], b[2*g+1][1], addr);
                }
                #pragma unroll
                for (int i = 0; i < 4; i++)
                    #pragma unroll
                    for (int jn = 0; jn < 8; jn++)
                        hmma(acc[i][jn], a[i][0], a[i][1], a[i][2], a[i][3],
                             b[jn][0], b[jn][1]);
            }
        }

        // ---- deferred B dequant + STS (LDG hidden under compute) ----
        if (fetch) {
            char* dst = sb + fB + tid * ROWB;
            uint4 q;
            q.x = dqw(p0.x); q.y = dqw(p0.y); q.z = dqw(p0.z); q.w = dqw(p0.w);
            *reinterpret_cast<uint4*>(dst + 0)  = q;
            q.x = dqw(p1.x); q.y = dqw(p1.y); q.z = dqw(p1.z); q.w = dqw(p1.w);
            *reinterpret_cast<uint4*>(dst + 16) = q;
            q.x = dqw(p2.x); q.y = dqw(p2.y); q.z = dqw(p2.z); q.w = dqw(p2.w);
            *reinterpret_cast<uint4*>(dst + 32) = q;
            q.x = dqw(p3.x); q.y = dqw(p3.y); q.z = dqw(p3.z); q.w = dqw(p3.w);
            *reinterpret_cast<uint4*>(dst + 48) = q;
        }
    }

    // ---- epilogue: scale + store fp32 ----
    #pragma unroll
    for (int i = 0; i < 4; i++) {
        int m0 = M0 + wm * 64 + i * 16 + (lid >> 2);
        #pragma unroll
        for (int j = 0; j < 8; j++) {
            int n = N0 + wn * 64 + j * 8 + 2 * (lid & 3);
            float2 s = *reinterpret_cast<const float2*>(scale + n);
            float2 o0, o1;
            o0.x = acc[i][j][0] * s.x;
            o0.y = acc[i][j][1] * s.y;
            o1.x = acc[i][j][2] * s.x;
            o1.y = acc[i][j][3] * s.y;
            *reinterpret_cast<float2*>(y + (size_t)m0 * N_DIM + n) = o0;
            *reinterpret_cast<float2*>(y + (size_t)(m0 + 8) * N_DIM + n) = o1;
        }
    }
}

// ---------------- launch ----------------
extern "C" void kernel_launch(void* const* d_in, const int* in_sizes, int n_in,
                              void* d_out, int out_size) {
    const float* x      = (const float*)d_in[0];
    const int*   packed = (const int*)  d_in[1];
    const float* scale  = (const float*)d_in[2];
    float*       y      = (float*)d_out;

    prep_kernel<<<XCONV_BLOCKS, 256>>>(x);

    static bool attr_set = false;
    if (!attr_set) {
        cudaFuncSetAttribute(qgemm_kernel,
                             cudaFuncAttributeMaxDynamicSharedMemorySize, SMEM_BYTES);
        attr_set = true;
    }
    dim3 grid(N_DIM / BN, M_DIM / BM);   // (64, 4) = 256 CTAs, 2/SM
    qgemm_kernel<<<grid, NTHREADS, SMEM_BYTES>>>(packed, scale, y);
}